// round 7
// baseline (speedup 1.0000x reference)
#include <cuda_runtime.h>
#include <math.h>
#include <string.h>

// ---------------------------------------------------------------------------
// Problem constants
// ---------------------------------------------------------------------------
#define NM_MAX 50000
#define ND_MAX 20000
#define EMAX   700000
#define FEAT   128
#define SCAN_CHUNK 2048   // elements per CSR-scan block (256 thr x 8)

// Scratch (device globals: allocation-free rule)
__device__ float g_agg1 [(size_t)NM_MAX * FEAT];
__device__ float g_movie[(size_t)NM_MAX * FEAT];
__device__ float g_agg2 [(size_t)ND_MAX * FEAT];
__device__ float g_user1[(size_t)ND_MAX * FEAT];
__device__ float g_agg3 [(size_t)ND_MAX * FEAT];
__device__ float g_user2[(size_t)ND_MAX * FEAT];

// CSR-build scratch
__device__ int   g_cnt_m[NM_MAX + 1];
__device__ int   g_off_m[NM_MAX + 1];
__device__ int   g_cur_m[NM_MAX];
__device__ int   g_perm_m[EMAX];
__device__ int   g_cnt_b[ND_MAX + 1];
__device__ int   g_off_b[ND_MAX + 1];
__device__ int   g_cur_b[ND_MAX];
__device__ int   g_perm_b[EMAX];
__device__ float g_ews[EMAX];     // sigmoid(edge_weight)
__device__ int   g_part_m[32];    // per-block partial sums (n <= 65536)
__device__ int   g_part_b[32];

// ---------------------------------------------------------------------------
// Helpers: packed f32x2 FMA (full-rate fp32 on sm_103a)
// ---------------------------------------------------------------------------
__device__ __forceinline__ void ffma2(unsigned long long& acc,
                                      unsigned long long a,
                                      unsigned long long b) {
    asm("fma.rn.f32x2 %0, %1, %2, %3;" : "=l"(acc) : "l"(a), "l"(b), "l"(acc));
}
__device__ __forceinline__ unsigned long long pack2(float lo, float hi) {
    unsigned long long r;
    asm("mov.b64 %0, {%1, %2};" : "=l"(r) : "f"(lo), "f"(hi));
    return r;
}

// ---------------------------------------------------------------------------
// CSR build
// ---------------------------------------------------------------------------
// Histogram both graphs + precompute sigmoid(ew). cnt arrays pre-zeroed by memset.
__global__ __launch_bounds__(256)
void hist_kernel(const int* __restrict__ dst_m, const int* __restrict__ dst_b,
                 const float* __restrict__ ew, int E) {
    int e = blockIdx.x * 256 + threadIdx.x;
    if (e >= E) return;
    atomicAdd(&g_cnt_m[__ldg(dst_m + e)], 1);
    atomicAdd(&g_cnt_b[__ldg(dst_b + e)], 1);
    g_ews[e] = 1.f / (1.f + __expf(-__ldg(ew + e)));
}

// Phase 1: per-block partial sums (both graphs packed in one grid)
__device__ __forceinline__ void reduce_body(const int* __restrict__ cnt,
                                            int* __restrict__ part, int n, int blk) {
    __shared__ int sw[8];
    int t = threadIdx.x;
    int base = blk * SCAN_CHUNK + t * 8;
    int s = 0;
#pragma unroll
    for (int j = 0; j < 8; ++j) {
        int i = base + j;
        if (i < n) s += __ldg(cnt + i);
    }
    // warp reduce
    for (int o = 16; o > 0; o >>= 1) s += __shfl_down_sync(0xffffffffu, s, o);
    if ((t & 31) == 0) sw[t >> 5] = s;
    __syncthreads();
    if (t < 8) {
        int v = sw[t];
        for (int o = 4; o > 0; o >>= 1) v += __shfl_down_sync(0xffu, v, o);
        if (t == 0) part[blk] = v;
    }
}
__global__ __launch_bounds__(256)
void csr_reduce(int n_m, int n_d, int nb_m) {
    if ((int)blockIdx.x < nb_m) reduce_body(g_cnt_m, g_part_m, n_m, blockIdx.x);
    else                        reduce_body(g_cnt_b, g_part_b, n_d, blockIdx.x - nb_m);
}

// Phase 2: tiny scan of partials (warp 0 -> m, warp 1 -> b), in-place exclusive
__global__ __launch_bounds__(64)
void csr_scanmid(int nb_m, int nb_b) {
    int w = threadIdx.x >> 5, lane = threadIdx.x & 31;
    int* part = w ? g_part_b : g_part_m;
    int  nb   = w ? nb_b : nb_m;
    int v = (lane < nb) ? part[lane] : 0;
    int x = v;
    for (int o = 1; o < 32; o <<= 1) {
        int y = __shfl_up_sync(0xffffffffu, x, o);
        if (lane >= o) x += y;
    }
    if (lane < nb) part[lane] = x - v;   // exclusive base per block
}

// Phase 3: per-block exclusive scan, write offs[] and cur[]; tail writes offs[n]
__device__ __forceinline__ void offs_body(const int* __restrict__ cnt,
                                          const int* __restrict__ part,
                                          int* __restrict__ offs, int* __restrict__ cur,
                                          int n, int blk) {
    __shared__ int sw[8];
    int t = threadIdx.x, lane = t & 31, wid = t >> 5;
    int base = blk * SCAN_CHUNK + t * 8;
    int c[8]; int s = 0;
#pragma unroll
    for (int j = 0; j < 8; ++j) {
        int i = base + j;
        c[j] = (i < n) ? __ldg(cnt + i) : 0;
        s += c[j];
    }
    // block exclusive scan of per-thread sums
    int x = s;
    for (int o = 1; o < 32; o <<= 1) {
        int y = __shfl_up_sync(0xffffffffu, x, o);
        if (lane >= o) x += y;
    }
    if (lane == 31) sw[wid] = x;
    __syncthreads();
    if (wid == 0) {
        int v = (lane < 8) ? sw[lane] : 0;
        for (int o = 1; o < 8; o <<= 1) {
            int y = __shfl_up_sync(0xffffffffu, v, o);
            if (lane >= o) v += y;
        }
        if (lane < 8) sw[lane] = v;
    }
    __syncthreads();
    int run = part[blk] + (wid ? sw[wid - 1] : 0) + x - s;  // global exclusive
#pragma unroll
    for (int j = 0; j < 8; ++j) {
        int i = base + j;
        if (i < n) {
            offs[i] = run;
            cur[i]  = run;
            run += c[j];
            if (i == n - 1) offs[n] = run;
        }
    }
}
__global__ __launch_bounds__(256)
void csr_offsets(int n_m, int n_d, int nb_m) {
    if ((int)blockIdx.x < nb_m)
        offs_body(g_cnt_m, g_part_m, g_off_m, g_cur_m, n_m, blockIdx.x);
    else
        offs_body(g_cnt_b, g_part_b, g_off_b, g_cur_b, n_d, blockIdx.x - nb_m);
}

// Phase 4: fill edge-id permutations for both graphs
__global__ __launch_bounds__(256)
void fill_kernel(const int* __restrict__ dst_m, const int* __restrict__ dst_b, int E) {
    int e = blockIdx.x * 256 + threadIdx.x;
    if (e >= E) return;
    int p = atomicAdd(&g_cur_m[__ldg(dst_m + e)], 1);
    g_perm_m[p] = e;
    int q = atomicAdd(&g_cur_b[__ldg(dst_b + e)], 1);
    g_perm_b[q] = e;
}

// ---------------------------------------------------------------------------
// Gather aggregation: one warp per dst node, no atomics.
// ---------------------------------------------------------------------------
__device__ __forceinline__ void agg_body(const float* __restrict__ x,
                                         const int*   __restrict__ src,
                                         const int*   __restrict__ perm,
                                         const int*   __restrict__ offs,
                                         float*       __restrict__ agg,
                                         int n_dst, int blk, bool weighted) {
    int d = blk * 8 + (threadIdx.x >> 5);
    if (d >= n_dst) return;
    const int lane  = threadIdx.x & 31;
    const int start = __ldg(offs + d);
    const int end   = __ldg(offs + d + 1);

    float4 acc = make_float4(0.f, 0.f, 0.f, 0.f);
    for (int base = start; base < end; base += 32) {
        int i = base + lane;
        int e = (i < end) ? __ldg(perm + i) : 0;
        int s = (i < end) ? __ldg(src + e) : 0;
        float w = 0.f;
        if (weighted) w = (i < end) ? __ldg(g_ews + e) : 0.f;
        int cnt = min(32, end - base);
        if (weighted) {
#pragma unroll 4
            for (int j = 0; j < cnt; ++j) {
                int   sj = __shfl_sync(0xffffffffu, s, j);
                float wj = __shfl_sync(0xffffffffu, w, j);
                float4 v = *reinterpret_cast<const float4*>(x + (size_t)sj * FEAT + lane * 4);
                acc.x = fmaf(wj, v.x, acc.x);
                acc.y = fmaf(wj, v.y, acc.y);
                acc.z = fmaf(wj, v.z, acc.z);
                acc.w = fmaf(wj, v.w, acc.w);
            }
        } else {
#pragma unroll 4
            for (int j = 0; j < cnt; ++j) {
                int sj = __shfl_sync(0xffffffffu, s, j);
                float4 v = *reinterpret_cast<const float4*>(x + (size_t)sj * FEAT + lane * 4);
                acc.x += v.x; acc.y += v.y; acc.z += v.z; acc.w += v.w;
            }
        }
    }
    *reinterpret_cast<float4*>(agg + (size_t)d * FEAT + lane * 4) = acc;
}

// Merged launch: agg1 (unweighted, m-graph) || agg2 (weighted, b-graph)
__global__ __launch_bounds__(256)
void agg_pair_kernel(const float* xA, const int* srcA, const int* permA,
                     const int* offsA, float* aggA, int nA, int nbA,
                     const float* xB, const int* srcB, const int* permB,
                     const int* offsB, float* aggB, int nB) {
    if ((int)blockIdx.x < nbA)
        agg_body(xA, srcA, permA, offsA, aggA, nA, blockIdx.x, false);
    else
        agg_body(xB, srcB, permB, offsB, aggB, nB, blockIdx.x - nbA, true);
}

__global__ __launch_bounds__(256)
void agg_single_kernel(const float* x, const int* src, const int* perm,
                       const int* offs, float* agg, int n_dst) {
    agg_body(x, src, perm, offs, agg, n_dst, blockIdx.x, true);
}

// ---------------------------------------------------------------------------
// Fused GraphConv GEMM body (double-buffered smem, 1 sync/k-tile):
//   out[m,n] = act( A1@W1 + (HAS2 ? A2@W2 : 0) + bias )
// ---------------------------------------------------------------------------
template <int BN, int TN, bool HAS2, bool RELU>
__device__ __forceinline__
void gemm_body(const float* __restrict__ A1, const float* __restrict__ W1,
               const float* __restrict__ A2, const float* __restrict__ W2,
               const float* __restrict__ bias,
               float* __restrict__ out, int M, int blk) {
    constexpr int BM = 128, BK = 8, K = 128, TM = 8;
    constexpr int TPP = K / BK;
    constexpr int NT  = HAS2 ? 2 * TPP : TPP;
    static_assert(BN == 16 * TN, "layout");

    __shared__ float sA[2][BK][BM + 4];
    __shared__ float sB[2][BK][BN + 4];

    const int t = threadIdx.x;
    const int rowBase = blk * BM;
    const int tm0 = (t / 16) * TM;
    const int tn0 = (t % 16) * TN;

    const int ar  = t >> 1;
    const int akk = (t & 1) * 4;
    const int agr = rowBase + ar;
    const bool bact = t < (BK * BN / 4);
    const int  bkr  = t / (BN / 4);
    const int  bnc  = (t % (BN / 4)) * 4;

    float4 ra, rb;
    auto loadRegs = [&](int tt) {
        const float* A = (HAS2 && tt >= TPP) ? A2 : A1;
        const float* W = (HAS2 && tt >= TPP) ? W2 : W1;
        const int kt = (HAS2 ? (tt % TPP) : tt) * BK;
        ra = make_float4(0.f, 0.f, 0.f, 0.f);
        if (agr < M)
            ra = *reinterpret_cast<const float4*>(A + (size_t)agr * K + kt + akk);
        if (bact)
            rb = *reinterpret_cast<const float4*>(W + (size_t)(kt + bkr) * BN + bnc);
    };
    auto storeRegs = [&](int buf) {
        sA[buf][akk + 0][ar] = ra.x;
        sA[buf][akk + 1][ar] = ra.y;
        sA[buf][akk + 2][ar] = ra.z;
        sA[buf][akk + 3][ar] = ra.w;
        if (bact)
            *reinterpret_cast<float4*>(&sB[buf][bkr][bnc]) = rb;
    };

    unsigned long long acc[TM][TN / 2] = {};

    loadRegs(0);
    storeRegs(0);
    __syncthreads();

#pragma unroll 1
    for (int tt = 0; tt < NT; ++tt) {
        const int cur = tt & 1;
        if (tt + 1 < NT) loadRegs(tt + 1);

        const float (*pA)[BM + 4] = sA[cur];
        const float (*pB)[BN + 4] = sB[cur];
#pragma unroll
        for (int k = 0; k < BK; ++k) {
            float4 a0 = *reinterpret_cast<const float4*>(&pA[k][tm0]);
            float4 a1 = *reinterpret_cast<const float4*>(&pA[k][tm0 + 4]);
            float av[TM] = {a0.x, a0.y, a0.z, a0.w, a1.x, a1.y, a1.z, a1.w};
            float4 bt[TN / 4];
#pragma unroll
            for (int jj = 0; jj < TN / 4; ++jj)
                bt[jj] = *reinterpret_cast<const float4*>(&pB[k][tn0 + 4 * jj]);
            unsigned long long bv[TN / 2];
            memcpy(bv, bt, sizeof(bt));
#pragma unroll
            for (int i = 0; i < TM; ++i) {
                unsigned long long ap = pack2(av[i], av[i]);
#pragma unroll
                for (int j = 0; j < TN / 2; ++j) ffma2(acc[i][j], ap, bv[j]);
            }
        }

        if (tt + 1 < NT) {
            storeRegs(cur ^ 1);
            __syncthreads();
        }
    }

#pragma unroll
    for (int i = 0; i < TM; ++i) {
        int gr = rowBase + tm0 + i;
        if (gr < M) {
#pragma unroll
            for (int j = 0; j < TN / 2; ++j) {
                float2 v;
                memcpy(&v, &acc[i][j], 8);
                float o0 = v.x + bias[tn0 + 2 * j];
                float o1 = v.y + bias[tn0 + 2 * j + 1];
                if (RELU) { o0 = fmaxf(o0, 0.f); o1 = fmaxf(o1, 0.f); }
                out[(size_t)gr * BN + tn0 + 2 * j]     = o0;
                out[(size_t)gr * BN + tn0 + 2 * j + 1] = o1;
            }
        }
    }
}

template <int BN, int TN, bool HAS2, bool RELU>
__global__ __launch_bounds__(256)
void gemm_single(const float* A1, const float* W1, const float* A2, const float* W2,
                 const float* bias, float* out, int M) {
    gemm_body<BN, TN, HAS2, RELU>(A1, W1, A2, W2, bias, out, M, blockIdx.x);
}

// Merged launch: two independent fused GraphConv GEMMs (same config)
__global__ __launch_bounds__(256)
void gemm_dual(const float* A1a, const float* W1a, const float* A2a, const float* W2a,
               const float* ba, float* oa, int Ma, int nb1,
               const float* A1b, const float* W1b, const float* A2b, const float* W2b,
               const float* bb, float* ob, int Mb) {
    if ((int)blockIdx.x < nb1)
        gemm_body<128, 8, true, true>(A1a, W1a, A2a, W2a, ba, oa, Ma, blockIdx.x);
    else
        gemm_body<128, 8, true, true>(A1b, W1b, A2b, W2b, bb, ob, Mb, blockIdx.x - nb1);
}

// ---------------------------------------------------------------------------
// Launch
// ---------------------------------------------------------------------------
extern "C" void kernel_launch(void* const* d_in, const int* in_sizes, int n_in,
                              void* d_out, int out_size) {
    const float* x_meas  = (const float*)d_in[0];
    const float* x_dem   = (const float*)d_in[1];
    const int*   src_m   = (const int*)  d_in[2];
    const int*   dst_m   = (const int*)  d_in[3];
    const int*   src_b   = (const int*)  d_in[4];
    const int*   dst_b   = (const int*)  d_in[5];
    const float* eweight = (const float*)d_in[6];
    const float* W_rel1  = (const float*)d_in[7];
    const float* b_rel1  = (const float*)d_in[8];
    const float* W_root1 = (const float*)d_in[9];
    const float* W_rel2  = (const float*)d_in[10];
    const float* b_rel2  = (const float*)d_in[11];
    const float* W_root2 = (const float*)d_in[12];
    const float* W_rel3  = (const float*)d_in[13];
    const float* b_rel3  = (const float*)d_in[14];
    const float* W_root3 = (const float*)d_in[15];
    const float* W_lin   = (const float*)d_in[16];
    const float* b_lin   = (const float*)d_in[17];
    float* out = (float*)d_out;

    const int n_m = in_sizes[0] / FEAT;
    const int n_d = in_sizes[1] / FEAT;
    const int E   = in_sizes[2];

    float *agg1, *agg2, *agg3, *movie, *user1, *user2;
    cudaGetSymbolAddress((void**)&agg1,  g_agg1);
    cudaGetSymbolAddress((void**)&agg2,  g_agg2);
    cudaGetSymbolAddress((void**)&agg3,  g_agg3);
    cudaGetSymbolAddress((void**)&movie, g_movie);
    cudaGetSymbolAddress((void**)&user1, g_user1);
    cudaGetSymbolAddress((void**)&user2, g_user2);
    int *cnt_m, *cnt_b, *off_m, *off_b, *cur_m, *cur_b, *perm_m, *perm_b;
    cudaGetSymbolAddress((void**)&cnt_m,  g_cnt_m);
    cudaGetSymbolAddress((void**)&cnt_b,  g_cnt_b);
    cudaGetSymbolAddress((void**)&off_m,  g_off_m);
    cudaGetSymbolAddress((void**)&off_b,  g_off_b);
    cudaGetSymbolAddress((void**)&cur_m,  g_cur_m);
    cudaGetSymbolAddress((void**)&cur_b,  g_cur_b);
    cudaGetSymbolAddress((void**)&perm_m, g_perm_m);
    cudaGetSymbolAddress((void**)&perm_b, g_perm_b);

    const int eb    = (E + 255) / 256;
    const int nb_m  = (n_m + SCAN_CHUNK - 1) / SCAN_CHUNK;   // <= 32
    const int nb_b  = (n_d + SCAN_CHUNK - 1) / SCAN_CHUNK;   // <= 32
    const int ba1   = (n_m + 7) / 8;
    const int ba2   = (n_d + 7) / 8;
    const int gb1   = (n_m + 127) / 128;
    const int gb2   = (n_d + 127) / 128;

    // --- CSR build (both graphs, parallel scan) ---
    cudaMemsetAsync(cnt_m, 0, (size_t)(n_m + 1) * sizeof(int));
    cudaMemsetAsync(cnt_b, 0, (size_t)(n_d + 1) * sizeof(int));
    hist_kernel<<<eb, 256>>>(dst_m, dst_b, eweight, E);
    csr_reduce<<<nb_m + nb_b, 256>>>(n_m, n_d, nb_m);
    csr_scanmid<<<1, 64>>>(nb_m, nb_b);
    csr_offsets<<<nb_m + nb_b, 256>>>(n_m, n_d, nb_m);
    fill_kernel<<<eb, 256>>>(dst_m, dst_b, E);

    // --- Layer 1 aggregations, merged (agg1 || agg2) ---
    agg_pair_kernel<<<ba1 + ba2, 256>>>(
        x_meas, src_m, perm_m, off_m, agg1, n_m, ba1,
        x_meas, src_b, perm_b, off_b, agg2, n_d);

    // --- Layer 1/2 GEMMs, merged ---
    gemm_dual<<<gb1 + gb2, 256>>>(
        agg1, W_rel1, x_meas, W_root1, b_rel1, movie, n_m, gb1,
        agg2, W_rel2, x_dem,  W_root2, b_rel2, user1, n_d);

    // --- Layer 3 aggregation + GEMM ---
    agg_single_kernel<<<ba2, 256>>>(movie, src_b, perm_b, off_b, agg3, n_d);
    gemm_single<128, 8, true, true><<<gb2, 256>>>(
        agg3, W_rel3, user1, W_root3, b_rel3, user2, n_d);

    // --- Output projection ---
    gemm_single<64, 4, false, false><<<gb2, 256>>>(
        user2, W_lin, nullptr, nullptr, b_lin, out, n_d);
}

// round 11
// speedup vs baseline: 1.5148x; 1.5148x over previous
#include <cuda_runtime.h>
#include <math.h>
#include <string.h>

// ---------------------------------------------------------------------------
// Problem constants
// ---------------------------------------------------------------------------
#define NM_MAX 50000
#define ND_MAX 20000
#define EMAX   700000
#define FEAT   128
#define SCAN_CHUNK 2048   // elements per CSR-scan block (256 thr x 8)

// Scratch (device globals: allocation-free rule)
__device__ float g_agg1 [(size_t)NM_MAX * FEAT];
__device__ float g_movie[(size_t)NM_MAX * FEAT];
__device__ float g_agg2 [(size_t)ND_MAX * FEAT];
__device__ float g_user1[(size_t)ND_MAX * FEAT];
__device__ float g_agg3 [(size_t)ND_MAX * FEAT];
__device__ float g_user2[(size_t)ND_MAX * FEAT];

// CSR-build scratch
__device__ int   g_cnt_m[NM_MAX + 1];
__device__ int   g_off_m[NM_MAX + 1];
__device__ int   g_cur_m[NM_MAX];
__device__ int   g_perm_m[EMAX];
__device__ int   g_cnt_b[ND_MAX + 1];
__device__ int   g_off_b[ND_MAX + 1];
__device__ int   g_cur_b[ND_MAX];
__device__ int   g_perm_b[EMAX];
__device__ float g_ews[EMAX];     // sigmoid(edge_weight)
__device__ int   g_part_m[32];    // per-block partial sums (n <= 65536)
__device__ int   g_part_b[32];

// ---------------------------------------------------------------------------
// Helpers: packed f32x2 FMA (full-rate fp32 on sm_103a)
// ---------------------------------------------------------------------------
__device__ __forceinline__ void ffma2(unsigned long long& acc,
                                      unsigned long long a,
                                      unsigned long long b) {
    asm("fma.rn.f32x2 %0, %1, %2, %3;" : "=l"(acc) : "l"(a), "l"(b), "l"(acc));
}
__device__ __forceinline__ unsigned long long pack2(float lo, float hi) {
    unsigned long long r;
    asm("mov.b64 %0, {%1, %2};" : "=l"(r) : "f"(lo), "f"(hi));
    return r;
}

// ---------------------------------------------------------------------------
// CSR build
// ---------------------------------------------------------------------------
// Histogram both graphs + precompute sigmoid(ew). cnt arrays pre-zeroed by memset.
__global__ __launch_bounds__(256)
void hist_kernel(const int* __restrict__ dst_m, const int* __restrict__ dst_b,
                 const float* __restrict__ ew, int E) {
    int e = blockIdx.x * 256 + threadIdx.x;
    if (e >= E) return;
    atomicAdd(&g_cnt_m[__ldg(dst_m + e)], 1);
    atomicAdd(&g_cnt_b[__ldg(dst_b + e)], 1);
    g_ews[e] = 1.f / (1.f + __expf(-__ldg(ew + e)));
}

// Phase 1: per-block partial sums (both graphs packed in one grid)
__device__ __forceinline__ void reduce_body(const int* __restrict__ cnt,
                                            int* __restrict__ part, int n, int blk) {
    __shared__ int sw[8];
    int t = threadIdx.x;
    int base = blk * SCAN_CHUNK + t * 8;
    int s = 0;
#pragma unroll
    for (int j = 0; j < 8; ++j) {
        int i = base + j;
        if (i < n) s += __ldg(cnt + i);
    }
    for (int o = 16; o > 0; o >>= 1) s += __shfl_down_sync(0xffffffffu, s, o);
    if ((t & 31) == 0) sw[t >> 5] = s;
    __syncthreads();
    if (t < 8) {
        int v = sw[t];
        for (int o = 4; o > 0; o >>= 1) v += __shfl_down_sync(0xffu, v, o);
        if (t == 0) part[blk] = v;
    }
}
__global__ __launch_bounds__(256)
void csr_reduce(int n_m, int n_d, int nb_m) {
    if ((int)blockIdx.x < nb_m) reduce_body(g_cnt_m, g_part_m, n_m, blockIdx.x);
    else                        reduce_body(g_cnt_b, g_part_b, n_d, blockIdx.x - nb_m);
}

// Phase 2: tiny scan of partials (warp 0 -> m, warp 1 -> b), in-place exclusive
__global__ __launch_bounds__(64)
void csr_scanmid(int nb_m, int nb_b) {
    int w = threadIdx.x >> 5, lane = threadIdx.x & 31;
    int* part = w ? g_part_b : g_part_m;
    int  nb   = w ? nb_b : nb_m;
    int v = (lane < nb) ? part[lane] : 0;
    int x = v;
    for (int o = 1; o < 32; o <<= 1) {
        int y = __shfl_up_sync(0xffffffffu, x, o);
        if (lane >= o) x += y;
    }
    if (lane < nb) part[lane] = x - v;   // exclusive base per block
}

// Phase 3: per-block exclusive scan, write offs[] and cur[]; tail writes offs[n]
__device__ __forceinline__ void offs_body(const int* __restrict__ cnt,
                                          const int* __restrict__ part,
                                          int* __restrict__ offs, int* __restrict__ cur,
                                          int n, int blk) {
    __shared__ int sw[8];
    int t = threadIdx.x, lane = t & 31, wid = t >> 5;
    int base = blk * SCAN_CHUNK + t * 8;
    int c[8]; int s = 0;
#pragma unroll
    for (int j = 0; j < 8; ++j) {
        int i = base + j;
        c[j] = (i < n) ? __ldg(cnt + i) : 0;
        s += c[j];
    }
    int x = s;
    for (int o = 1; o < 32; o <<= 1) {
        int y = __shfl_up_sync(0xffffffffu, x, o);
        if (lane >= o) x += y;
    }
    if (lane == 31) sw[wid] = x;
    __syncthreads();
    if (wid == 0) {
        int v = (lane < 8) ? sw[lane] : 0;
        for (int o = 1; o < 8; o <<= 1) {
            int y = __shfl_up_sync(0xffffffffu, v, o);
            if (lane >= o) v += y;
        }
        if (lane < 8) sw[lane] = v;
    }
    __syncthreads();
    int run = part[blk] + (wid ? sw[wid - 1] : 0) + x - s;  // global exclusive
#pragma unroll
    for (int j = 0; j < 8; ++j) {
        int i = base + j;
        if (i < n) {
            offs[i] = run;
            cur[i]  = run;
            run += c[j];
            if (i == n - 1) offs[n] = run;
        }
    }
}
__global__ __launch_bounds__(256)
void csr_offsets(int n_m, int n_d, int nb_m) {
    if ((int)blockIdx.x < nb_m)
        offs_body(g_cnt_m, g_part_m, g_off_m, g_cur_m, n_m, blockIdx.x);
    else
        offs_body(g_cnt_b, g_part_b, g_off_b, g_cur_b, n_d, blockIdx.x - nb_m);
}

// Phase 4: fill edge-id permutations for both graphs
__global__ __launch_bounds__(256)
void fill_kernel(const int* __restrict__ dst_m, const int* __restrict__ dst_b, int E) {
    int e = blockIdx.x * 256 + threadIdx.x;
    if (e >= E) return;
    int p = atomicAdd(&g_cur_m[__ldg(dst_m + e)], 1);
    g_perm_m[p] = e;
    int q = atomicAdd(&g_cur_b[__ldg(dst_b + e)], 1);
    g_perm_b[q] = e;
}

// ---------------------------------------------------------------------------
// Gather-based aggregation: one warp per dst node. Edge meta loaded in
// chunks of 32 (lane-parallel, coalesced), broadcast via shfl; each lane
// accumulates 4 of the 128 features. No atomics, agg fully overwritten.
// ---------------------------------------------------------------------------
template <bool WEIGHTED>
__global__ __launch_bounds__(256)
void agg_gather(const float* __restrict__ x,
                const int*   __restrict__ src,
                const int*   __restrict__ perm,
                const int*   __restrict__ offs,
                float*       __restrict__ agg,
                int n_dst) {
    int d = blockIdx.x * 8 + (threadIdx.x >> 5);
    if (d >= n_dst) return;
    const int lane  = threadIdx.x & 31;
    const int start = __ldg(offs + d);
    const int end   = __ldg(offs + d + 1);

    float4 acc = make_float4(0.f, 0.f, 0.f, 0.f);
    for (int base = start; base < end; base += 32) {
        int i = base + lane;
        int e = (i < end) ? __ldg(perm + i) : 0;
        int s = (i < end) ? __ldg(src + e) : 0;
        float w = 1.f;
        if (WEIGHTED) w = (i < end) ? __ldg(g_ews + e) : 0.f;
        int cnt = min(32, end - base);
#pragma unroll 4
        for (int j = 0; j < cnt; ++j) {
            int   sj = __shfl_sync(0xffffffffu, s, j);
            float wj = WEIGHTED ? __shfl_sync(0xffffffffu, w, j) : 1.f;
            float4 v = *reinterpret_cast<const float4*>(x + (size_t)sj * FEAT + lane * 4);
            if (WEIGHTED) {
                acc.x = fmaf(wj, v.x, acc.x);
                acc.y = fmaf(wj, v.y, acc.y);
                acc.z = fmaf(wj, v.z, acc.z);
                acc.w = fmaf(wj, v.w, acc.w);
            } else {
                acc.x += v.x; acc.y += v.y; acc.z += v.z; acc.w += v.w;
            }
        }
    }
    *reinterpret_cast<float4*>(agg + (size_t)d * FEAT + lane * 4) = acc;
}

// ---------------------------------------------------------------------------
// Fused GraphConv GEMM, double-buffered smem pipeline, 1 sync per k-tile:
//   out[m,n] = act( A1[m,:]@W1[:,n] + (HAS2 ? A2[m,:]@W2[:,n] : 0) + bias[n] )
// K=128 per pass, BM=128, BK=8, 256 threads, thread tile 8 x TN, BN=16*TN.
// ---------------------------------------------------------------------------
template <int BN, int TN, bool HAS2, bool RELU>
__global__ __launch_bounds__(256)
void gemm_fused(const float* __restrict__ A1, const float* __restrict__ W1,
                const float* __restrict__ A2, const float* __restrict__ W2,
                const float* __restrict__ bias,
                float* __restrict__ out, int M) {
    constexpr int BM = 128, BK = 8, K = 128, TM = 8;
    constexpr int TPP = K / BK;                 // tiles per pass = 16
    constexpr int NT  = HAS2 ? 2 * TPP : TPP;   // total k-tiles
    static_assert(BN == 16 * TN, "layout");

    __shared__ float sA[2][BK][BM + 4];
    __shared__ float sB[2][BK][BN + 4];

    const int t = threadIdx.x;
    const int rowBase = blockIdx.x * BM;
    const int tm0 = (t / 16) * TM;
    const int tn0 = (t % 16) * TN;

    const int ar  = t >> 1;
    const int akk = (t & 1) * 4;
    const int agr = rowBase + ar;
    const bool bact = t < (BK * BN / 4);
    const int  bkr  = t / (BN / 4);
    const int  bnc  = (t % (BN / 4)) * 4;

    float4 ra, rb;
    auto loadRegs = [&](int tt) {
        const float* A = (HAS2 && tt >= TPP) ? A2 : A1;
        const float* W = (HAS2 && tt >= TPP) ? W2 : W1;
        const int kt = (HAS2 ? (tt % TPP) : tt) * BK;
        ra = make_float4(0.f, 0.f, 0.f, 0.f);
        if (agr < M)
            ra = *reinterpret_cast<const float4*>(A + (size_t)agr * K + kt + akk);
        if (bact)
            rb = *reinterpret_cast<const float4*>(W + (size_t)(kt + bkr) * BN + bnc);
    };
    auto storeRegs = [&](int buf) {
        sA[buf][akk + 0][ar] = ra.x;
        sA[buf][akk + 1][ar] = ra.y;
        sA[buf][akk + 2][ar] = ra.z;
        sA[buf][akk + 3][ar] = ra.w;
        if (bact)
            *reinterpret_cast<float4*>(&sB[buf][bkr][bnc]) = rb;
    };

    unsigned long long acc[TM][TN / 2] = {};  // 0 == {+0.f,+0.f}

    loadRegs(0);
    storeRegs(0);
    __syncthreads();

#pragma unroll 1
    for (int tt = 0; tt < NT; ++tt) {
        const int cur = tt & 1;
        if (tt + 1 < NT) loadRegs(tt + 1);

        const float (*pA)[BM + 4] = sA[cur];
        const float (*pB)[BN + 4] = sB[cur];
#pragma unroll
        for (int k = 0; k < BK; ++k) {
            float4 a0 = *reinterpret_cast<const float4*>(&pA[k][tm0]);
            float4 a1 = *reinterpret_cast<const float4*>(&pA[k][tm0 + 4]);
            float av[TM] = {a0.x, a0.y, a0.z, a0.w, a1.x, a1.y, a1.z, a1.w};
            float4 bt[TN / 4];
#pragma unroll
            for (int jj = 0; jj < TN / 4; ++jj)
                bt[jj] = *reinterpret_cast<const float4*>(&pB[k][tn0 + 4 * jj]);
            unsigned long long bv[TN / 2];
            memcpy(bv, bt, sizeof(bt));
#pragma unroll
            for (int i = 0; i < TM; ++i) {
                unsigned long long ap = pack2(av[i], av[i]);
#pragma unroll
                for (int j = 0; j < TN / 2; ++j) ffma2(acc[i][j], ap, bv[j]);
            }
        }

        if (tt + 1 < NT) {
            storeRegs(cur ^ 1);
            __syncthreads();
        }
    }

    // --- epilogue: bias (+ReLU) + store ---
#pragma unroll
    for (int i = 0; i < TM; ++i) {
        int gr = rowBase + tm0 + i;
        if (gr < M) {
#pragma unroll
            for (int j = 0; j < TN / 2; ++j) {
                float2 v;
                memcpy(&v, &acc[i][j], 8);
                float o0 = v.x + bias[tn0 + 2 * j];
                float o1 = v.y + bias[tn0 + 2 * j + 1];
                if (RELU) { o0 = fmaxf(o0, 0.f); o1 = fmaxf(o1, 0.f); }
                out[(size_t)gr * BN + tn0 + 2 * j]     = o0;
                out[(size_t)gr * BN + tn0 + 2 * j + 1] = o1;
            }
        }
    }
}

// ---------------------------------------------------------------------------
// Launch
// ---------------------------------------------------------------------------
extern "C" void kernel_launch(void* const* d_in, const int* in_sizes, int n_in,
                              void* d_out, int out_size) {
    const float* x_meas  = (const float*)d_in[0];
    const float* x_dem   = (const float*)d_in[1];
    const int*   src_m   = (const int*)  d_in[2];
    const int*   dst_m   = (const int*)  d_in[3];
    const int*   src_b   = (const int*)  d_in[4];
    const int*   dst_b   = (const int*)  d_in[5];
    const float* eweight = (const float*)d_in[6];
    const float* W_rel1  = (const float*)d_in[7];
    const float* b_rel1  = (const float*)d_in[8];
    const float* W_root1 = (const float*)d_in[9];
    const float* W_rel2  = (const float*)d_in[10];
    const float* b_rel2  = (const float*)d_in[11];
    const float* W_root2 = (const float*)d_in[12];
    const float* W_rel3  = (const float*)d_in[13];
    const float* b_rel3  = (const float*)d_in[14];
    const float* W_root3 = (const float*)d_in[15];
    const float* W_lin   = (const float*)d_in[16];
    const float* b_lin   = (const float*)d_in[17];
    float* out = (float*)d_out;

    const int n_m = in_sizes[0] / FEAT;
    const int n_d = in_sizes[1] / FEAT;
    const int E   = in_sizes[2];

    float *agg1, *agg2, *agg3, *movie, *user1, *user2;
    cudaGetSymbolAddress((void**)&agg1,  g_agg1);
    cudaGetSymbolAddress((void**)&agg2,  g_agg2);
    cudaGetSymbolAddress((void**)&agg3,  g_agg3);
    cudaGetSymbolAddress((void**)&movie, g_movie);
    cudaGetSymbolAddress((void**)&user1, g_user1);
    cudaGetSymbolAddress((void**)&user2, g_user2);
    int *cnt_m, *cnt_b, *off_m, *off_b, *cur_m, *cur_b, *perm_m, *perm_b;
    cudaGetSymbolAddress((void**)&cnt_m,  g_cnt_m);
    cudaGetSymbolAddress((void**)&cnt_b,  g_cnt_b);
    cudaGetSymbolAddress((void**)&off_m,  g_off_m);
    cudaGetSymbolAddress((void**)&off_b,  g_off_b);
    cudaGetSymbolAddress((void**)&cur_m,  g_cur_m);
    cudaGetSymbolAddress((void**)&cur_b,  g_cur_b);
    cudaGetSymbolAddress((void**)&perm_m, g_perm_m);
    cudaGetSymbolAddress((void**)&perm_b, g_perm_b);

    const int eb   = (E + 255) / 256;
    const int nb_m = (n_m + SCAN_CHUNK - 1) / SCAN_CHUNK;   // <= 32
    const int nb_b = (n_d + SCAN_CHUNK - 1) / SCAN_CHUNK;   // <= 32

    // --- CSR build (both graphs, parallel 3-phase scan) ---
    cudaMemsetAsync(cnt_m, 0, (size_t)(n_m + 1) * sizeof(int));
    cudaMemsetAsync(cnt_b, 0, (size_t)(n_d + 1) * sizeof(int));
    hist_kernel<<<eb, 256>>>(dst_m, dst_b, eweight, E);
    csr_reduce<<<nb_m + nb_b, 256>>>(n_m, n_d, nb_m);
    csr_scanmid<<<1, 64>>>(nb_m, nb_b);
    csr_offsets<<<nb_m + nb_b, 256>>>(n_m, n_d, nb_m);
    fill_kernel<<<eb, 256>>>(dst_m, dst_b, E);

    // --- Layer 1 aggregations (gather, no atomics) ---
    agg_gather<false><<<(n_m + 7) / 8, 256>>>(x_meas, src_m, perm_m, off_m, agg1, n_m);
    agg_gather<true ><<<(n_d + 7) / 8, 256>>>(x_meas, src_b, perm_b, off_b, agg2, n_d);

    // --- Layer 1/2 GEMMs ---
    gemm_fused<128, 8, true, true><<<(n_m + 127) / 128, 256>>>(
        agg1, W_rel1, x_meas, W_root1, b_rel1, movie, n_m);
    gemm_fused<128, 8, true, true><<<(n_d + 127) / 128, 256>>>(
        agg2, W_rel2, x_dem, W_root2, b_rel2, user1, n_d);

    // --- Layer 3 aggregation (reuses bipartite CSR) + GEMM ---
    agg_gather<true><<<(n_d + 7) / 8, 256>>>(movie, src_b, perm_b, off_b, agg3, n_d);
    gemm_fused<128, 8, true, true><<<(n_d + 127) / 128, 256>>>(
        agg3, W_rel3, user1, W_root3, b_rel3, user2, n_d);

    // --- Output projection ---
    gemm_fused<64, 4, false, false><<<(n_d + 127) / 128, 256>>>(
        user2, W_lin, nullptr, nullptr, b_lin, out, n_d);
}